// round 12
// baseline (speedup 1.0000x reference)
#include <cuda_runtime.h>

// TransD scoring: out = h - t + r + rp * ((hp.h) - (tp.t))
// One warp per row; lane i handles one float4 (D=128, D/4=32 == warp width).
//
// FINAL-candidate (minimal variant of the roofline-bound config):
// ~643MB irreducible traffic (512MB random entity gathers + 128MB streaming
// writes + indices) at ~6.4-6.5TB/s effective = B300 mixed-R/W ceiling.
//  - 512-thread blocks (best granularity; 256/1024/persistent all tested)
//  - 6 front-batched LDG.128 per warp + warp-count latency hiding
//  - plain __ldg loads (L2 policy hints measured as noise R4-R11)
//  - __stcs streaming stores
//  - warp butterfly reduction, both dot products combined into one pass

static constexpr int DV4 = 32;  // 128 floats / 4

__global__ __launch_bounds__(512) void transd_kernel(
    const int* __restrict__ head,
    const int* __restrict__ relation,
    const int* __restrict__ tail,
    const float4* __restrict__ ent_emb,
    const float4* __restrict__ ent_map_emb,
    const float4* __restrict__ rel_emb,
    const float4* __restrict__ rel_map_emb,
    float4* __restrict__ out,
    int B)
{
    int gtid = blockIdx.x * blockDim.x + threadIdx.x;
    int row  = gtid >> 5;
    int lane = gtid & 31;
    if (row >= B) return;

    // Index loads: broadcast within warp.
    int hi = __ldg(&head[row]);
    int ri = __ldg(&relation[row]);
    int ti = __ldg(&tail[row]);

    long hoff = (long)hi * DV4 + lane;
    long toff = (long)ti * DV4 + lane;
    long roff = (long)ri * DV4 + lane;

    // Front-batch all 6 independent loads for MLP.
    float4 hv = __ldg(&ent_emb[hoff]);
    float4 hp = __ldg(&ent_map_emb[hoff]);
    float4 tv = __ldg(&ent_emb[toff]);
    float4 tp = __ldg(&ent_map_emb[toff]);
    float4 rv = __ldg(&rel_emb[roff]);
    float4 rp = __ldg(&rel_map_emb[roff]);

    // Per-lane partial dot products; combine before reduction.
    float sh = hv.x * hp.x + hv.y * hp.y + hv.z * hp.z + hv.w * hp.w;
    float st = tv.x * tp.x + tv.y * tp.y + tv.z * tp.z + tv.w * tp.w;
    float s = sh - st;

    // Warp butterfly reduction.
    #pragma unroll
    for (int o = 16; o > 0; o >>= 1) {
        s += __shfl_xor_sync(0xffffffffu, s, o);
    }

    float4 o4;
    o4.x = hv.x - tv.x + rv.x + rp.x * s;
    o4.y = hv.y - tv.y + rv.y + rp.y * s;
    o4.z = hv.z - tv.z + rv.z + rp.z * s;
    o4.w = hv.w - tv.w + rv.w + rp.w * s;

    // Streaming store: keep the 128MB output stream out of L2's way.
    __stcs(&out[(long)row * DV4 + lane], o4);
}

extern "C" void kernel_launch(void* const* d_in, const int* in_sizes, int n_in,
                              void* d_out, int out_size)
{
    const int*    head    = (const int*)d_in[0];
    const int*    rel     = (const int*)d_in[1];
    const int*    tail    = (const int*)d_in[2];
    const float4* ent     = (const float4*)d_in[3];
    const float4* ent_map = (const float4*)d_in[4];
    const float4* rel_e   = (const float4*)d_in[5];
    const float4* rel_map = (const float4*)d_in[6];
    float4*       out     = (float4*)d_out;

    int B = in_sizes[0];
    int blocks = (B + 15) / 16;   // 16 warps (rows) per 512-thread block
    transd_kernel<<<blocks, 512>>>(head, rel, tail, ent, ent_map, rel_e, rel_map, out, B);
}

// round 13
// speedup vs baseline: 1.0108x; 1.0108x over previous
#include <cuda_runtime.h>

// TransD scoring: out = h - t + r + rp * ((hp.h) - (tp.t))
// One warp per row; lane i handles one float4 (D=128, D/4=32 == warp width).
//
// FINAL (R8 configuration — best bench of 13 rounds, 98.34us):
// Roofline-bound: ~643MB irreducible traffic (512MB random 512B-row entity
// gathers + 128MB streaming writes + 3MB indices), moved at ~6.5TB/s
// effective = measured B300 mixed-R/W LTS/DRAM ceiling. DRAM 82% busy,
// issue 22% — warps park on an already-saturated memory system.
//
// Tested and rejected: 2 rows/warp (occupancy loss), 1024-thr blocks (tail
// imbalance), persistent grid-stride (reg bloat, occ 48%), head-bucket
// permutation (+22us prep, scattered writes erase gather locality).
// Noise-equivalent: all L2 hints, deferred relation loads, 256-thr blocks.
//
//  - 512-thread blocks, 16 warps (rows) per CTA, 16384 CTAs
//  - 6 front-batched LDG.128 per warp (per-warp MLP) + warp-count hiding
//  - entity gathers: evict_last L2 policy; output: write-through store
//  - both dot products combined before a single warp butterfly reduction

static constexpr int DV4 = 32;  // 128 floats / 4

__device__ __forceinline__ float4 ldg_evl(const float4* p, unsigned long long pol) {
    float4 v;
    asm volatile("ld.global.nc.L2::cache_hint.v4.f32 {%0,%1,%2,%3}, [%4], %5;"
                 : "=f"(v.x), "=f"(v.y), "=f"(v.z), "=f"(v.w)
                 : "l"(p), "l"(pol));
    return v;
}

__global__ __launch_bounds__(512) void transd_kernel(
    const int* __restrict__ head,
    const int* __restrict__ relation,
    const int* __restrict__ tail,
    const float4* __restrict__ ent_emb,
    const float4* __restrict__ ent_map_emb,
    const float4* __restrict__ rel_emb,
    const float4* __restrict__ rel_map_emb,
    float4* __restrict__ out,
    int B)
{
    int gtid = blockIdx.x * blockDim.x + threadIdx.x;
    int row  = gtid >> 5;
    int lane = gtid & 31;
    if (row >= B) return;

    unsigned long long pol;
    asm volatile("createpolicy.fractional.L2::evict_last.b64 %0, 1.0;" : "=l"(pol));

    // Index loads: broadcast within warp.
    int hi = __ldg(&head[row]);
    int ri = __ldg(&relation[row]);
    int ti = __ldg(&tail[row]);

    long hoff = (long)hi * DV4 + lane;
    long toff = (long)ti * DV4 + lane;
    long roff = (long)ri * DV4 + lane;

    // Front-batch all 6 independent loads for MLP.
    float4 hv = ldg_evl(&ent_emb[hoff], pol);
    float4 hp = ldg_evl(&ent_map_emb[hoff], pol);
    float4 tv = ldg_evl(&ent_emb[toff], pol);
    float4 tp = ldg_evl(&ent_map_emb[toff], pol);
    float4 rv = __ldg(&rel_emb[roff]);
    float4 rp = __ldg(&rel_map_emb[roff]);

    // Per-lane partial dot products; combine before reduction.
    float sh = hv.x * hp.x + hv.y * hp.y + hv.z * hp.z + hv.w * hp.w;
    float st = tv.x * tp.x + tv.y * tp.y + tv.z * tp.z + tv.w * tp.w;
    float s = sh - st;

    // Warp butterfly reduction.
    #pragma unroll
    for (int o = 16; o > 0; o >>= 1) {
        s += __shfl_xor_sync(0xffffffffu, s, o);
    }

    float4 o4;
    o4.x = hv.x - tv.x + rv.x + rp.x * s;
    o4.y = hv.y - tv.y + rv.y + rp.y * s;
    o4.z = hv.z - tv.z + rv.z + rp.z * s;
    o4.w = hv.w - tv.w + rv.w + rp.w * s;

    // Write-through store: don't allocate L2 for the 128MB output stream.
    __stwt(&out[(long)row * DV4 + lane], o4);
}

extern "C" void kernel_launch(void* const* d_in, const int* in_sizes, int n_in,
                              void* d_out, int out_size)
{
    const int*    head    = (const int*)d_in[0];
    const int*    rel     = (const int*)d_in[1];
    const int*    tail    = (const int*)d_in[2];
    const float4* ent     = (const float4*)d_in[3];
    const float4* ent_map = (const float4*)d_in[4];
    const float4* rel_e   = (const float4*)d_in[5];
    const float4* rel_map = (const float4*)d_in[6];
    float4*       out     = (float4*)d_out;

    int B = in_sizes[0];
    int blocks = (B + 15) / 16;   // 16 warps (rows) per 512-thread block
    transd_kernel<<<blocks, 512>>>(head, rel, tail, ent, ent_map, rel_e, rel_map, out, B);
}